// round 12
// baseline (speedup 1.0000x reference)
#include <cuda_runtime.h>
#include <cstdint>

// ChannelExchangeWithConv: N=1, C=128, H=W=512, p=2
// R10 base (1D warp map, pipelined copy) with copy LDG->STG distance deepened
// to 4 k-blocks (~720 cyc > 577-cyc DRAM latency).

#define HW    262144
#define TP    128
#define CH    64
#define WROW  68
#define NT    (HW / TP)       // 2048 tiles per direction
#define NJOBS (2 * NT)        // 4096
#define NCTAS 296             // 2 per SM

typedef unsigned long long u64;

__device__ __forceinline__ u64 pkdup(float x) {
    u64 r; asm("mov.b64 %0, {%1, %1};" : "=l"(r) : "f"(x)); return r;
}
__device__ __forceinline__ u64 pk2(float x, float y) {
    u64 r; asm("mov.b64 %0, {%1, %2};" : "=l"(r) : "f"(x), "f"(y)); return r;
}
__device__ __forceinline__ void unpk(u64 v, float& lo, float& hi) {
    asm("mov.b64 {%0, %1}, %2;" : "=f"(lo), "=f"(hi) : "l"(v));
}
#define FMA2(acc, a, b) \
    asm("fma.rn.f32x2 %0, %1, %2, %0;" : "+l"(acc) : "l"(a), "l"(b))

__device__ __forceinline__ void cpasync16(uint32_t s, const void* g) {
    asm volatile("cp.async.cg.shared.global [%0], [%1], 16;" :: "r"(s), "l"(g));
}

__global__ __launch_bounds__(256, 2)
void cx_kernel(const float* __restrict__ lst, const float* __restrict__ gui,
               const float* __restrict__ w1,  const float* __restrict__ b1,
               const float* __restrict__ w2,  const float* __restrict__ b2,
               float* __restrict__ out)
{
    extern __shared__ float smem[];
    float* Xbuf = smem;                         // [2][64][128] double-buffered x tiles
    float* Wt   = smem + 2 * CH * TP;           // [2][64][68]
    float* Bs   = Wt + 2 * CH * WROW;           // [2][64]

    const int tid = threadIdx.x;
    const int bx  = blockIdx.x;

    // --- stage BOTH weight sets (transposed) + biases, once per CTA ---
    #pragma unroll
    for (int i = 0; i < 32; i++) {
        int idx = i * 256 + tid;
        int d   = idx >> 12;
        int o   = (idx >> 6) & 63;
        int c   = idx & 63;
        const float* W = d ? w1 : w2;
        Wt[(d * CH + c) * WROW + o] = W[o * CH + c];
    }
    if (tid < 2 * CH) Bs[tid] = (tid < CH) ? b2[tid] : b1[tid - CH];

    // x-tile cp.async mapping: [64 rows][32 float4 cols]
    const int lrow = tid >> 5;
    const int lcol = (tid & 31) << 2;
    // copy mapping
    const int crow = tid >> 5;
    const int ccol = (tid & 31) << 2;

    const uint32_t sX0 = (uint32_t)__cvta_generic_to_shared(Xbuf);
    const uint32_t sX1 = (uint32_t)__cvta_generic_to_shared(Xbuf + CH * TP);

    // GEMM mapping (R10): 8 warps = 8 o-groups; thread tile 4px x 8o
    const int warp  = tid >> 5;
    const int q     = tid & 31;
    const int px    = 4 * q;
    const int obase = warp * 8;

    // --- prologue: prefetch job0 x-tile into buf0 ---
    {
        int j = bx;
        int dir = j >> 11, tile = j & (NT - 1);
        const float* xin = dir ? lst : gui;
        const float* gp  = xin + (size_t)tile * TP + lcol;
        #pragma unroll
        for (int i = 0; i < 8; i++) {
            cpasync16(sX0 + (uint32_t)((lrow + 8 * i) * TP + lcol) * 4,
                      gp + (size_t)(2 * (lrow + 8 * i)) * HW);
        }
        asm volatile("cp.async.commit_group;");
    }

    int it = 0;
    for (int j = bx; j < NJOBS; j += NCTAS, it++) {
        const int cur = it & 1;
        const int dir = j >> 11, tile = j & (NT - 1);
        const int pix0 = tile * TP;
        const float* cpin = dir ? gui : lst;
        float* oo = out + (size_t)dir * 128 * HW;

        asm volatile("cp.async.wait_group 0;");
        __syncthreads();

        const float* Xs = Xbuf + cur * CH * TP;
        const float* Wd = Wt + dir * CH * WROW + obase;
        const float* Bd = Bs + dir * CH;

        // next-tile prefetch params (issued spread over blocks 0..3)
        const int jn = j + NCTAS;
        const bool havenext = (jn < NJOBS);
        const int dn = jn >> 11, tn = jn & (NT - 1);
        const float* gpN = (dn ? lst : gui) + (size_t)tn * TP + lcol;
        const uint32_t sdst = cur ? sX0 : sX1;

        // acc init with bias
        u64 acc[4][4];
        #pragma unroll
        for (int jj = 0; jj < 4; jj++) {
            u64 bb = pk2(Bd[obase + 2 * jj], Bd[obase + 2 * jj + 1]);
            acc[0][jj] = bb; acc[1][jj] = bb; acc[2][jj] = bb; acc[3][jj] = bb;
        }

        const float* xp = Xs + px;
        const float* cbase = cpin + pix0 + ccol;
        float*       obuf  = oo + pix0 + ccol;

        // copy pipeline preload: chunks 0..3 in flight (MLP=4, > DRAM latency cover)
        float4 cpv[8];
        #pragma unroll
        for (int i = 0; i < 4; i++)
            cpv[i] = *(const float4*)(cbase + (size_t)(2 * (i * 8 + crow) + 1) * HW);

        // --- k-loop: 8 blocks x 8 k; per block: 1 copy LDG (b+4), 1 copy STG (b) ---
        #pragma unroll
        for (int b = 0; b < 8; b++) {
            if (b < 4 && havenext) {
                cpasync16(sdst + (uint32_t)((lrow + 8 * (2 * b)) * TP + lcol) * 4,
                          gpN + (size_t)(2 * (lrow + 8 * (2 * b))) * HW);
                cpasync16(sdst + (uint32_t)((lrow + 8 * (2 * b + 1)) * TP + lcol) * 4,
                          gpN + (size_t)(2 * (lrow + 8 * (2 * b + 1))) * HW);
            }
            if (b == 3 && havenext)
                asm volatile("cp.async.commit_group;");

            if (b < 4)
                cpv[b + 4] = *(const float4*)(cbase + (size_t)(2 * ((b + 4) * 8 + crow) + 1) * HW);

            #pragma unroll
            for (int cc = 0; cc < 8; cc++) {
                const int c = b * 8 + cc;
                float4 xv = *(const float4*)(xp + c * TP);
                u64 x0 = pkdup(xv.x), x1 = pkdup(xv.y), x2 = pkdup(xv.z), x3 = pkdup(xv.w);
                const u64* wr = (const u64*)(Wd + c * WROW);
                ulonglong2 wa = *(const ulonglong2*)(wr);
                ulonglong2 wb = *(const ulonglong2*)(wr + 2);
                u64 w[4] = {wa.x, wa.y, wb.x, wb.y};
                #pragma unroll
                for (int jj = 0; jj < 4; jj++) {
                    FMA2(acc[0][jj], w[jj], x0);
                    FMA2(acc[1][jj], w[jj], x1);
                    FMA2(acc[2][jj], w[jj], x2);
                    FMA2(acc[3][jj], w[jj], x3);
                }
            }

            *(float4*)(obuf + (size_t)(2 * (b * 8 + crow) + 1) * HW) = cpv[b];
        }

        // GEMM output stores: pair jj = conv o (obase+2jj,+1) -> global ch 2*obase+4jj,+2
        #pragma unroll
        for (int jj = 0; jj < 4; jj++) {
            float a0, a1, b0v, b1v, c0, c1, d0, d1;
            unpk(acc[0][jj], a0, a1);
            unpk(acc[1][jj], b0v, b1v);
            unpk(acc[2][jj], c0, c1);
            unpk(acc[3][jj], d0, d1);
            size_t ch0 = (size_t)2 * obase + 4 * jj;
            *(float4*)(oo + ch0 * HW + pix0 + px)       = make_float4(a0, b0v, c0, d0);
            *(float4*)(oo + (ch0 + 2) * HW + pix0 + px) = make_float4(a1, b1v, c1, d1);
        }
    }
}

extern "C" void kernel_launch(void* const* d_in, const int* in_sizes, int n_in,
                              void* d_out, int out_size)
{
    const float* lst = (const float*)d_in[0];
    const float* gui = (const float*)d_in[1];
    const float* w1  = (const float*)d_in[2];
    const float* b1  = (const float*)d_in[3];
    const float* w2  = (const float*)d_in[4];
    const float* b2  = (const float*)d_in[5];
    float* out = (float*)d_out;

    const size_t smem = (size_t)2 * CH * TP * 4 + (size_t)2 * CH * WROW * 4 + 2 * CH * 4; // 100864 B
    cudaFuncSetAttribute(cx_kernel, cudaFuncAttributeMaxDynamicSharedMemorySize, (int)smem);

    cx_kernel<<<NCTAS, 256, smem>>>(lst, gui, w1, b1, w2, b2, out);
}

// round 13
// speedup vs baseline: 1.1257x; 1.1257x over previous
#include <cuda_runtime.h>
#include <cstdint>

// ChannelExchangeWithConv: N=1, C=128, H=W=512, p=2
// TF32 tensor-core GEMM (mma.sync m16n8k8), W fragments register-resident,
// persistent 2-CTA/SM, cp.async double-buffered x, pipelined passthrough copy.

#define HW    262144
#define TP    128
#define XROW  136             // padded smem row (conflict-free B fragments)
#define CH    64
#define NT    (HW / TP)       // 2048 tiles per direction
#define NJOBS (2 * NT)        // 4096
#define NCTAS 296             // 2 per SM

__device__ __forceinline__ void cpasync16(uint32_t s, const void* g) {
    asm volatile("cp.async.cg.shared.global [%0], [%1], 16;" :: "r"(s), "l"(g));
}
__device__ __forceinline__ uint32_t f2tf32(float f) {
    uint32_t r; asm("cvt.rna.tf32.f32 %0, %1;" : "=r"(r) : "f"(f)); return r;
}
#define MMA_TF32(c0,c1,c2,c3, a0,a1,a2,a3, b0,b1) \
    asm("mma.sync.aligned.m16n8k8.row.col.f32.tf32.tf32.f32 " \
        "{%0,%1,%2,%3},{%4,%5,%6,%7},{%8,%9},{%0,%1,%2,%3};" \
        : "+f"(c0), "+f"(c1), "+f"(c2), "+f"(c3) \
        : "r"(a0), "r"(a1), "r"(a2), "r"(a3), "r"(b0), "r"(b1))

__global__ __launch_bounds__(256, 2)
void cx_kernel(const float* __restrict__ lst, const float* __restrict__ gui,
               const float* __restrict__ w1,  const float* __restrict__ b1,
               const float* __restrict__ w2,  const float* __restrict__ b2,
               float* __restrict__ out)
{
    extern __shared__ float smem[];
    float* Xbuf = smem;                       // [2][64][136] double-buffered x tiles
    float* Bsm  = smem + 2 * CH * XROW;       // [2][64] biases

    const int tid  = threadIdx.x;
    const int bx   = blockIdx.x;
    const int lane = tid & 31;

    if (tid < 2 * CH) Bsm[tid] = (tid < CH) ? b2[tid] : b1[tid - CH];

    // cp.async x-tile mapping: [64 rows][32 float4], thread's i-th chunk row = lrow+8i
    const int lrow = tid >> 5;
    const int lcol4 = (tid & 31);             // float4 col
    // copy mapping (odd channels)
    const int crow = tid >> 5;
    const int ccol = (tid & 31) << 2;

    const uint32_t sX0 = (uint32_t)__cvta_generic_to_shared(Xbuf);
    const uint32_t sX1 = (uint32_t)__cvta_generic_to_shared(Xbuf + CH * XROW);

    // mma mapping: 8 warps = 4 o-groups (M=16) x 2 px-halves (N=64)
    const int warp = tid >> 5;
    const int o0   = (warp >> 1) * 16;
    const int pxb  = (warp & 1) * 64;
    const int gid  = lane >> 2;               // 0..7
    const int tig  = lane & 3;                // 0..3

    // --- prologue: prefetch job0 x-tile into buf0 ---
    {
        int dir = bx >> 11, tile = bx & (NT - 1);
        const float* gp = (dir ? lst : gui) + (size_t)tile * TP + lcol4 * 4;
        #pragma unroll
        for (int i = 0; i < 8; i++) {
            int row = lrow + 8 * i;
            cpasync16(sX0 + (uint32_t)(row * XROW + lcol4 * 4) * 4,
                      gp + (size_t)(2 * row) * HW);
        }
        asm volatile("cp.async.commit_group;");
    }
    __syncthreads();   // Bsm visible

    uint32_t afr[8][4];                        // W fragments, tf32, all K
    int dprev = -1;

    int it = 0;
    for (int j = bx; j < NJOBS; j += NCTAS, it++) {
        const int cur = it & 1;
        const int dir = j >> 11, tile = j & (NT - 1);
        const int pix0 = tile * TP;
        const float* cpin = dir ? gui : lst;
        float* oo = out + (size_t)dir * 128 * HW;

        // reload W fragments on direction change (rare: once per CTA)
        if (dir != dprev) {
            const float* W = dir ? w1 : w2;
            #pragma unroll
            for (int kb = 0; kb < 8; kb++) {
                int c0i = kb * 8 + tig;
                afr[kb][0] = f2tf32(W[(o0 + gid) * CH + c0i]);
                afr[kb][1] = f2tf32(W[(o0 + gid + 8) * CH + c0i]);
                afr[kb][2] = f2tf32(W[(o0 + gid) * CH + c0i + 4]);
                afr[kb][3] = f2tf32(W[(o0 + gid + 8) * CH + c0i + 4]);
            }
            dprev = dir;
        }

        asm volatile("cp.async.wait_group 0;");
        __syncthreads();

        const float* Xs = Xbuf + cur * CH * XROW;

        // next-tile prefetch params
        const int jn = j + NCTAS;
        const bool havenext = (jn < NJOBS);
        const int dn = jn >> 11, tn = jn & (NT - 1);
        const float* gpN = (dn ? lst : gui) + (size_t)tn * TP + lcol4 * 4;
        const uint32_t sdst = cur ? sX0 : sX1;

        // acc init with bias
        const float blo = Bsm[dir * CH + o0 + gid];
        const float bhi = Bsm[dir * CH + o0 + gid + 8];
        float acc[8][4];
        #pragma unroll
        for (int nb = 0; nb < 8; nb++) {
            acc[nb][0] = blo; acc[nb][1] = blo;
            acc[nb][2] = bhi; acc[nb][3] = bhi;
        }

        const float* cbase = cpin + pix0 + ccol;
        float*       obuf  = oo + pix0 + ccol;

        // copy pipeline preload (R10 schedule): chunks 0,1
        float4 cpv[8];
        cpv[0] = *(const float4*)(cbase + (size_t)(2 * (0 * 8 + crow) + 1) * HW);
        cpv[1] = *(const float4*)(cbase + (size_t)(2 * (1 * 8 + crow) + 1) * HW);

        const float* xb = Xs + pxb + gid;      // + nb*8 cols, + row*XROW

        // --- k-loop: 8 k-blocks; copy + prefetch threaded through ---
        #pragma unroll
        for (int kb = 0; kb < 8; kb++) {
            if (kb < 4 && havenext) {
                int r0 = lrow + 8 * (2 * kb), r1 = lrow + 8 * (2 * kb + 1);
                cpasync16(sdst + (uint32_t)(r0 * XROW + lcol4 * 4) * 4,
                          gpN + (size_t)(2 * r0) * HW);
                cpasync16(sdst + (uint32_t)(r1 * XROW + lcol4 * 4) * 4,
                          gpN + (size_t)(2 * r1) * HW);
            }
            if (kb == 3 && havenext)
                asm volatile("cp.async.commit_group;");

            const float* xk0 = xb + (kb * 8 + tig) * XROW;
            const float* xk1 = xk0 + 4 * XROW;
            #pragma unroll
            for (int nb = 0; nb < 8; nb++) {
                uint32_t b0 = f2tf32(xk0[nb * 8]);
                uint32_t b1 = f2tf32(xk1[nb * 8]);
                MMA_TF32(acc[nb][0], acc[nb][1], acc[nb][2], acc[nb][3],
                         afr[kb][0], afr[kb][1], afr[kb][2], afr[kb][3], b0, b1);
            }

            if (kb < 6)
                cpv[kb + 2] = *(const float4*)(cbase + (size_t)(2 * ((kb + 2) * 8 + crow) + 1) * HW);
            *(float4*)(obuf + (size_t)(2 * (kb * 8 + crow) + 1) * HW) = cpv[kb];
        }

        // epilogue: D[o][px]; rows o0+gid, o0+gid+8 -> even global channels 2*o
        #pragma unroll
        for (int nb = 0; nb < 8; nb++) {
            int pxp = pxb + nb * 8 + tig * 2;
            float* olo = oo + (size_t)(2 * (o0 + gid)) * HW + pix0 + pxp;
            float* ohi = oo + (size_t)(2 * (o0 + gid + 8)) * HW + pix0 + pxp;
            *(float2*)olo = make_float2(acc[nb][0], acc[nb][1]);
            *(float2*)ohi = make_float2(acc[nb][2], acc[nb][3]);
        }
    }
}

extern "C" void kernel_launch(void* const* d_in, const int* in_sizes, int n_in,
                              void* d_out, int out_size)
{
    const float* lst = (const float*)d_in[0];
    const float* gui = (const float*)d_in[1];
    const float* w1  = (const float*)d_in[2];
    const float* b1  = (const float*)d_in[3];
    const float* w2  = (const float*)d_in[4];
    const float* b2  = (const float*)d_in[5];
    float* out = (float*)d_out;

    const size_t smem = (size_t)2 * CH * XROW * 4 + 2 * CH * 4; // 70144 B
    cudaFuncSetAttribute(cx_kernel, cudaFuncAttributeMaxDynamicSharedMemorySize, (int)smem);

    cx_kernel<<<NCTAS, 256, smem>>>(lst, gui, w1, b1, w2, b2, out);
}